// round 1
// baseline (speedup 1.0000x reference)
#include <cuda_runtime.h>
#include <cstdint>

// ---------------- problem constants ----------------
#define BB      64          // batch
#define PP      56          // grid side
#define N_TOK   3136        // P*P
#define DIMC    256         // input channels
#define HEADS   4
#define HDIM    24
#define CH      96          // HEADS*HDIM
#define CH2     192         // feat+val
#define MCNT    16          // cluster centers
#define BH      256         // B*HEADS
#define OUTC    256
#define MTOT    (BB * N_TOK)   // 200704 rows

// ---------------- scratch (device globals; no allocation allowed) ----------------
__device__ float g_w12[CH2 * DIMC];            // [192,256] concat of f_w, v_w
__device__ float g_b12[CH2];
__device__ float g_fv[(size_t)MTOT * CH2];     // [B,N,192]   feat(0:96) | val(96:192)
__device__ float g_cn[BH * MCNT * HDIM];       // l2-normalized feat centers
__device__ float g_vc[BH * MCNT * HDIM];       // raw value centers
__device__ float g_agg[BH * MCNT * HDIM];
__device__ float g_s[(size_t)BH * N_TOK];      // top-1 sim value (post leaky)
__device__ unsigned char g_m[(size_t)BH * N_TOK]; // top-1 center index
__device__ float g_merged[(size_t)MTOT * CH];  // [B,N,96] dispatched tokens

// ---------------- K0: concat weights/biases ----------------
__global__ void k_concat(const float* __restrict__ fw, const float* __restrict__ fb,
                         const float* __restrict__ vw, const float* __restrict__ vb) {
    int i = blockIdx.x * blockDim.x + threadIdx.x;
    if (i < CH * DIMC)                 g_w12[i] = fw[i];
    else if (i < CH2 * DIMC)           g_w12[i] = vw[i - CH * DIMC];
    else if (i < CH2 * DIMC + CH)      g_b12[i - CH2 * DIMC] = fb[i - CH2 * DIMC];
    else if (i < CH2 * DIMC + CH2)     g_b12[i - CH2 * DIMC] = vb[i - CH2 * DIMC - CH];
}

// ---------------- generic fp32 GEMM:  C[M,NC] = A[M,K] @ W[NC,K]^T + bias ----------------
// BM=128, BN=64, BK=8, 128 threads, 8x8 per thread. M % 128 == 0, NC % 64 == 0, K % 8 == 0.
template <int K, int NC>
__device__ __forceinline__ void gemm_body(const float* __restrict__ A,
                                          const float* __restrict__ W,
                                          const float* __restrict__ bias,
                                          float* __restrict__ C) {
    __shared__ float As[8][128];
    __shared__ float Bs[8][64];
    const int tid = threadIdx.x;
    const int m0 = blockIdx.x * 128;
    const int n0 = blockIdx.y * 64;
    const int ty = tid >> 3;          // 0..15 -> 8 rows each
    const int tx = tid & 7;           // 0..7  -> 8 cols each

    const float* Ap = A + (size_t)(m0 + tid) * K;
    const int br = tid >> 1;          // 0..63
    const int bk = (tid & 1) * 4;
    const float* Wp = W + (size_t)(n0 + br) * K + bk;

    float4 a0 = *(const float4*)(Ap);
    float4 a1 = *(const float4*)(Ap + 4);
    float4 b0 = *(const float4*)(Wp);

    float acc[8][8];
#pragma unroll
    for (int i = 0; i < 8; i++)
#pragma unroll
        for (int j = 0; j < 8; j++) acc[i][j] = 0.f;

    const int KT = K / 8;
    for (int kt = 0; kt < KT; ++kt) {
        As[0][tid] = a0.x; As[1][tid] = a0.y; As[2][tid] = a0.z; As[3][tid] = a0.w;
        As[4][tid] = a1.x; As[5][tid] = a1.y; As[6][tid] = a1.z; As[7][tid] = a1.w;
        Bs[bk + 0][br] = b0.x; Bs[bk + 1][br] = b0.y; Bs[bk + 2][br] = b0.z; Bs[bk + 3][br] = b0.w;
        __syncthreads();
        if (kt + 1 < KT) {
            a0 = *(const float4*)(Ap + (kt + 1) * 8);
            a1 = *(const float4*)(Ap + (kt + 1) * 8 + 4);
            b0 = *(const float4*)(Wp + (kt + 1) * 8);
        }
#pragma unroll
        for (int k = 0; k < 8; k++) {
            float ra[8], rb[8];
            *(float4*)(ra)     = *(const float4*)&As[k][ty * 8];
            *(float4*)(ra + 4) = *(const float4*)&As[k][ty * 8 + 4];
            *(float4*)(rb)     = *(const float4*)&Bs[k][tx * 8];
            *(float4*)(rb + 4) = *(const float4*)&Bs[k][tx * 8 + 4];
#pragma unroll
            for (int i = 0; i < 8; i++)
#pragma unroll
                for (int j = 0; j < 8; j++) acc[i][j] += ra[i] * rb[j];
        }
        __syncthreads();
    }

    float bb[8];
#pragma unroll
    for (int j = 0; j < 8; j++) bb[j] = bias[n0 + tx * 8 + j];
#pragma unroll
    for (int i = 0; i < 8; i++) {
        float* Cp = C + (size_t)(m0 + ty * 8 + i) * NC + n0 + tx * 8;
        float4 o0, o1;
        o0.x = acc[i][0] + bb[0]; o0.y = acc[i][1] + bb[1];
        o0.z = acc[i][2] + bb[2]; o0.w = acc[i][3] + bb[3];
        o1.x = acc[i][4] + bb[4]; o1.y = acc[i][5] + bb[5];
        o1.z = acc[i][6] + bb[6]; o1.w = acc[i][7] + bb[7];
        *(float4*)(Cp) = o0;
        *(float4*)(Cp + 4) = o1;
    }
}

__global__ void k_gemm_fv(const float* __restrict__ x) {
    gemm_body<DIMC, CH2>(x, g_w12, g_b12, g_fv);
}
__global__ void k_gemm_proj(const float* __restrict__ pw, const float* __restrict__ pb,
                            float* __restrict__ out) {
    gemm_body<CH, OUTC>(g_merged, pw, pb, out);
}

// ---------------- K2: 4x4 adaptive-avg pooling + center l2-norm ----------------
// grid (BH, 16), 192 threads: c = t%48 (0..23 feat, 24..47 val), sub = t/48 (4 token strips)
__global__ void k_pool() {
    int bh = blockIdx.x, m = blockIdx.y;
    int b = bh >> 2, e = bh & 3;
    int t = threadIdx.x;
    int c = t % 48, sub = t / 48;
    int w0 = (m >> 2) * 14, h0 = (m & 3) * 14;
    int off = (c < 24) ? (e * HDIM + c) : (CH + e * HDIM + (c - 24));
    float acc = 0.f;
    for (int ti = sub; ti < 196; ti += 4) {
        int n = (w0 + ti / 14) * PP + h0 + ti % 14;
        acc += g_fv[((size_t)b * N_TOK + n) * CH2 + off];
    }
    __shared__ float red[4][48];
    __shared__ float meanv[48];
    __shared__ float sinv;
    red[sub][c] = acc;
    __syncthreads();
    if (t < 48) meanv[t] = (red[0][t] + red[1][t] + red[2][t] + red[3][t]) * (1.f / 196.f);
    __syncthreads();
    if (t == 0) {
        float s = 0.f;
        for (int i = 0; i < 24; i++) s += meanv[i] * meanv[i];
        sinv = 1.f / fmaxf(sqrtf(s), 1e-12f);
    }
    __syncthreads();
    if (t < 24)      g_cn[(bh * MCNT + m) * HDIM + t] = meanv[t] * sinv;
    else if (t < 48) g_vc[(bh * MCNT + m) * HDIM + (t - 24)] = meanv[t];
}

// ---------------- K3a: per-token cosine-sim, leaky-relu, top-1 assignment ----------------
__global__ void k_assign(const float* __restrict__ alpha_p, const float* __restrict__ beta_p) {
    int bh = blockIdx.x;
    int b = bh >> 2, e = bh & 3;
    __shared__ float cnT[24][16];   // c-major for vectorized reads
    int t = threadIdx.x;
    for (int i = t; i < 384; i += 256) {
        int m = i / 24, c = i % 24;
        cnT[c][m] = g_cn[(bh * MCNT + m) * HDIM + c];
    }
    __syncthreads();
    float alpha = alpha_p[0], beta = beta_p[0];
    for (int n = t; n < N_TOK; n += 256) {
        const float* fp = g_fv + ((size_t)b * N_TOK + n) * CH2 + e * HDIM;
        float f[24];
#pragma unroll
        for (int i = 0; i < 6; i++) *(float4*)(f + 4 * i) = *(const float4*)(fp + 4 * i);
        float ss = 0.f;
#pragma unroll
        for (int c = 0; c < 24; c++) ss += f[c] * f[c];
        float inv = 1.f / fmaxf(sqrtf(ss), 1e-12f);
        float dm[16];
#pragma unroll
        for (int m = 0; m < 16; m++) dm[m] = 0.f;
#pragma unroll
        for (int c = 0; c < 24; c++) {
            float fc = f[c];
#pragma unroll
            for (int m = 0; m < 16; m++) dm[m] += cnT[c][m] * fc;
        }
        float best = -1e30f; int bm = 0;
#pragma unroll
        for (int m = 0; m < 16; m++) {
            float v = beta + alpha * (dm[m] * inv);
            v = (v > 0.f) ? v : 0.2f * v;            // leaky_relu 0.2
            if (v > best) { best = v; bm = m; }       // first-max == jnp.argmax
        }
        g_s[(size_t)bh * N_TOK + n] = best;
        g_m[(size_t)bh * N_TOK + n] = (unsigned char)bm;
    }
}

// ---------------- K3b: per-(bh,m) masked aggregation  agg = (sum s*v + vc)/(count+1) ----------------
__global__ void k_agg() {
    int bh = blockIdx.x, m = blockIdx.y;
    int b = bh >> 2, e = bh & 3;
    int t = threadIdx.x;          // 128
    float acc[24];
#pragma unroll
    for (int c = 0; c < 24; c++) acc[c] = 0.f;
    float cnt = 0.f;
    for (int n = t; n < N_TOK; n += 128) {
        if (g_m[(size_t)bh * N_TOK + n] == (unsigned char)m) {
            float s = g_s[(size_t)bh * N_TOK + n];
            const float* vp = g_fv + ((size_t)b * N_TOK + n) * CH2 + CH + e * HDIM;
            float vv[24];
#pragma unroll
            for (int i = 0; i < 6; i++) *(float4*)(vv + 4 * i) = *(const float4*)(vp + 4 * i);
#pragma unroll
            for (int c = 0; c < 24; c++) acc[c] += s * vv[c];
            cnt += 1.f;
        }
    }
    __shared__ float wsum[4][24];
    __shared__ float wcnt[4];
    int lane = t & 31, wp = t >> 5;
#pragma unroll
    for (int c = 0; c < 24; c++) {
        float v = acc[c];
        for (int o = 16; o; o >>= 1) v += __shfl_down_sync(0xffffffffu, v, o);
        if (lane == 0) wsum[wp][c] = v;
    }
    {
        float v = cnt;
        for (int o = 16; o; o >>= 1) v += __shfl_down_sync(0xffffffffu, v, o);
        if (lane == 0) wcnt[wp] = v;
    }
    __syncthreads();
    if (t < 24) {
        float s = wsum[0][t] + wsum[1][t] + wsum[2][t] + wsum[3][t];
        float ct = wcnt[0] + wcnt[1] + wcnt[2] + wcnt[3];
        int idx = (bh * MCNT + m) * HDIM + t;
        g_agg[idx] = (s + g_vc[idx]) / (ct + 1.f);
    }
}

// ---------------- K4: dispatch back to tokens, head-merged layout ----------------
// grid BH, 192 threads: 8 tokens x 24 channels per iteration
__global__ void k_dispatch() {
    int bh = blockIdx.x;
    int b = bh >> 2, e = bh & 3;
    __shared__ float agg[16][24];
    int t = threadIdx.x;
    for (int i = t; i < 384; i += 192) agg[i / 24][i % 24] = g_agg[bh * 384 + i];
    __syncthreads();
    int c = t % 24, tl = t / 24;
    for (int n0 = 0; n0 < N_TOK; n0 += 8) {
        int n = n0 + tl;
        float s = g_s[(size_t)bh * N_TOK + n];
        int mm = g_m[(size_t)bh * N_TOK + n];
        g_merged[((size_t)b * N_TOK + n) * CH + e * HDIM + c] = s * agg[mm][c];
    }
}

// ---------------- launch ----------------
extern "C" void kernel_launch(void* const* d_in, const int* in_sizes, int n_in,
                              void* d_out, int out_size) {
    const float* x       = (const float*)d_in[0];
    const float* f_w     = (const float*)d_in[1];
    const float* f_b     = (const float*)d_in[2];
    const float* v_w     = (const float*)d_in[3];
    const float* v_b     = (const float*)d_in[4];
    const float* proj_w  = (const float*)d_in[5];
    const float* proj_b  = (const float*)d_in[6];
    const float* sim_a   = (const float*)d_in[7];
    const float* sim_b   = (const float*)d_in[8];
    float* out = (float*)d_out;

    k_concat<<<(CH2 * DIMC + CH2 + 255) / 256, 256>>>(f_w, f_b, v_w, v_b);
    k_gemm_fv<<<dim3(MTOT / 128, CH2 / 64), 128>>>(x);
    k_pool<<<dim3(BH, MCNT), 192>>>();
    k_assign<<<BH, 256>>>(sim_a, sim_b);
    k_agg<<<dim3(BH, MCNT), 128>>>();
    k_dispatch<<<BH, 192>>>();
    k_gemm_proj<<<dim3(MTOT / 128, OUTC / 64), 128>>>(proj_w, proj_b, out);
}